// round 6
// baseline (speedup 1.0000x reference)
#include <cuda_runtime.h>

// MeanAggregator: out[b] = mean over DISTINCT sampled neighbors of features[nbrs[b,s]]
// features: float32 [N=200000, D=256]   (d_in[0])
// nbrs:     int32   [B=32768, S=10]     (d_in[1])
// out:      float32 [B, D]              (d_out)
//
// 1 warp per row; each lane owns 8 floats (32B). Gathers use Blackwell
// 256-bit loads (ld.global.cg.v8.f32): one warp fetches a full 1KB feature
// row in a single LDG.E.256 -> half the wavefronts of the float4 version.

#define D 256
#define S 10
#define ROWS_PER_CTA 8

__global__ __launch_bounds__(32 * ROWS_PER_CTA)
void mean_agg_kernel(const float* __restrict__ feat,
                     const int* __restrict__ nbrs,
                     float* __restrict__ out,
                     int B)
{
    const int row = blockIdx.x * ROWS_PER_CTA + threadIdx.y;   // grid exact
    const int lane = threadIdx.x;            // 0..31, owns floats [lane*8, lane*8+8)

    // Vectorized index load: 40 bytes per row, 8-byte aligned -> 5x int2.
    const int2* __restrict__ nb2 =
        reinterpret_cast<const int2*>(nbrs + (long long)row * S);
    int idx[S];
#pragma unroll
    for (int i = 0; i < 5; ++i) {
        int2 p = nb2[i];
        idx[2 * i]     = p.x;
        idx[2 * i + 1] = p.y;
    }

    // Dup mask: bit i set if idx[i] repeats an earlier index. 45 compares.
    unsigned mask = 0;
    float n = 0.f;
#pragma unroll
    for (int i = 0; i < S; ++i) {
        bool dup = false;
#pragma unroll
        for (int j = 0; j < i; ++j) dup |= (idx[j] == idx[i]);
        mask |= dup ? (1u << i) : 0u;
        n += dup ? 0.f : 1.f;
    }

    // Unconditional weighted gathers via 256-bit loads (L2-only caching;
    // no reuse below L2). 10 independent LDG.E.256 per thread.
    float acc[8] = {0.f, 0.f, 0.f, 0.f, 0.f, 0.f, 0.f, 0.f};
#pragma unroll
    for (int i = 0; i < S; ++i) {
        const float* p = feat + (long long)idx[i] * D + lane * 8;  // 32B aligned
        float v0, v1, v2, v3, v4, v5, v6, v7;
        asm("ld.global.cg.v8.f32 {%0,%1,%2,%3,%4,%5,%6,%7}, [%8];"
            : "=f"(v0), "=f"(v1), "=f"(v2), "=f"(v3),
              "=f"(v4), "=f"(v5), "=f"(v6), "=f"(v7)
            : "l"(p));
        const float wi = (mask & (1u << i)) ? 0.f : 1.f;
        acc[0] = fmaf(wi, v0, acc[0]);
        acc[1] = fmaf(wi, v1, acc[1]);
        acc[2] = fmaf(wi, v2, acc[2]);
        acc[3] = fmaf(wi, v3, acc[3]);
        acc[4] = fmaf(wi, v4, acc[4]);
        acc[5] = fmaf(wi, v5, acc[5]);
        acc[6] = fmaf(wi, v6, acc[6]);
        acc[7] = fmaf(wi, v7, acc[7]);
    }

    const float inv = 1.f / n;
    float4 o0, o1;
    o0.x = acc[0] * inv;  o0.y = acc[1] * inv;
    o0.z = acc[2] * inv;  o0.w = acc[3] * inv;
    o1.x = acc[4] * inv;  o1.y = acc[5] * inv;
    o1.z = acc[6] * inv;  o1.w = acc[7] * inv;

    float4* obase = reinterpret_cast<float4*>(out + (long long)row * D + lane * 8);
    __stcs(obase,     o0);
    __stcs(obase + 1, o1);
}

extern "C" void kernel_launch(void* const* d_in, const int* in_sizes, int n_in,
                              void* d_out, int out_size)
{
    const float* feat = (const float*)d_in[0];
    const int*   nbrs = (const int*)d_in[1];
    float*       out  = (float*)d_out;

    const int B = in_sizes[1] / S;           // 32768

    dim3 block(32, ROWS_PER_CTA);
    dim3 grid(B / ROWS_PER_CTA);
    mean_agg_kernel<<<grid, block>>>(feat, nbrs, out, B);
}